// round 12
// baseline (speedup 1.0000x reference)
#include <cuda_runtime.h>
#include <cuda_bf16.h>
#include <math.h>
#include <stdint.h>

// ---------------- scratch ----------------
__device__ float g_bufA[800L*64*42*42];   // conv1 out (NHWC)
__device__ float g_bufB[800L*64*21*21];   // conv2 out (NHWC)
__device__ float g_bufC[800L*64*11*11];   // conv3 out (NHWC)
__device__ float g_bufD[800L*2304];       // conv4 out (embeddings, NHWC-flat)
__device__ float g_protos[8*5*2304];
__device__ float g_protoInv[8*5];
// conv1 weights tf32: [k(32)][cout]
__device__ float g_w1t[32*64];
// conv2/3/4 weights bf16x2 words: [tap(9)][cout(64)][cin word(32)]
__device__ uint32_t g_w2b[9*2048];
__device__ uint32_t g_w3b[9*2048];
__device__ uint32_t g_w4b[9*2048];

__device__ __forceinline__ float tf32_rna(float x) {
    uint32_t r; asm("cvt.rna.tf32.f32 %0, %1;" : "=r"(r) : "f"(x));
    return __uint_as_float(r);
}
__device__ __forceinline__ uint32_t bf16x2(float lo, float hi) {
    uint32_t r; asm("cvt.rn.bf16x2.f32 %0, %1, %2;" : "=r"(r) : "f"(hi), "f"(lo));
    return r;
}

// ---------------- weight prepacks ----------------
__global__ void prepack_wb(const float* __restrict__ w, uint32_t* __restrict__ wb)
{
    int gid = blockIdx.x * 256 + threadIdx.x;          // 9*2048
    if (gid >= 9*2048) return;
    int tap  = gid / 2048;
    int r    = gid & 2047;
    int cout = r >> 5;
    int cw   = r & 31;
    float v0 = w[(cout*64 + cw*2    )*9 + tap];
    float v1 = w[(cout*64 + cw*2 + 1)*9 + tap];
    wb[gid] = bf16x2(v0, v1);
}

__global__ void prepack_w1(const float* __restrict__ w, float* __restrict__ wt)
{
    int gid = blockIdx.x * 256 + threadIdx.x;          // 32*64
    if (gid >= 32*64) return;
    int k    = gid >> 6;
    int cout = gid & 63;
    float v = 0.f;
    if (k < 27) {
        int c = k / 9, tap = k - 9*c;
        v = tf32_rna(w[(cout*3 + c)*9 + tap]);
    }
    wt[gid] = v;
}

// ---------------- conv1: mma.sync tf32, NCHW in -> NHWC out ----------------
#define A1P 36
#define B1P 72

__global__ void __launch_bounds__(256)
conv1_mma(const float* __restrict__ in, const float* __restrict__ wt,
          const float* __restrict__ bias, float* __restrict__ out)
{
    __shared__ float sA[128*A1P];
    __shared__ float sB[32*B1P];
    __shared__ float sbias[64];

    const int tid  = threadIdx.x;
    const int wid  = tid >> 5;
    const int lane = tid & 31;
    const int n    = blockIdx.x;
    const int oy0  = blockIdx.y * 3;

    if (tid < 64) sbias[tid] = bias[tid];

    // ---- stage A: 2 threads per position, 14 taps each ----
    {
        const int p   = tid >> 1;
        const int h   = tid & 1;
        const int oyl = p / 42;
        const int oxp = p - oyl*42;
        const int oy  = oy0 + oyl;
        const bool pv = p < 126;
        const float* ib = in + (size_t)n*3*84*84;
        float* dst = sA + p*A1P;
        for (int k = h*14; k < h*14 + 14; k++) {
            if (k < 27) {
                int c = k / 9, rem = k - 9*c;
                int ky = rem / 3, kx = rem - 3*(rem/3);
                int ry = 2*oy + ky, rx = 2*oxp + kx;
                float v = 0.f;
                if (pv && ry < 84 && rx < 84)
                    v = ib[(c*84 + ry)*84 + rx];
                dst[k] = tf32_rna(v);
            }
        }
        if (h) { dst[27]=0.f; dst[28]=0.f; dst[29]=0.f; dst[30]=0.f; dst[31]=0.f; }
    }
    // ---- stage B: threads 0..127, 4 float4 each ----
    if (tid < 128) {
        const float4* bsrc = (const float4*)wt;
#pragma unroll
        for (int i = 0; i < 4; i++) {
            int idx = tid + i*128;
            int row = idx >> 4, col4 = idx & 15;
            *(float4*)(sB + row*B1P + col4*4) = bsrc[idx];
        }
    }
    __syncthreads();

    const int wm = (wid & 3) * 32;
    const int wn = (wid >> 2) * 32;

    float c[2][4][4];
#pragma unroll
    for (int i = 0; i < 2; i++)
#pragma unroll
        for (int j = 0; j < 4; j++)
#pragma unroll
            for (int q = 0; q < 4; q++) c[i][j][q] = 0.f;

#pragma unroll
    for (int ks = 0; ks < 4; ks++) {
        const int k0 = ks*8;
        uint32_t a[2][4];
#pragma unroll
        for (int mi = 0; mi < 2; mi++) {
            const float* ap = sA + (wm + mi*16 + (lane>>2))*A1P + k0 + (lane&3);
            a[mi][0] = __float_as_uint(ap[0]);
            a[mi][1] = __float_as_uint(ap[8*A1P]);
            a[mi][2] = __float_as_uint(ap[4]);
            a[mi][3] = __float_as_uint(ap[8*A1P + 4]);
        }
        uint32_t b[4][2];
#pragma unroll
        for (int ni = 0; ni < 4; ni++) {
            const float* bp = sB + (k0 + (lane&3))*B1P + wn + ni*8 + (lane>>2);
            b[ni][0] = __float_as_uint(bp[0]);
            b[ni][1] = __float_as_uint(bp[4*B1P]);
        }
#pragma unroll
        for (int mi = 0; mi < 2; mi++)
#pragma unroll
            for (int ni = 0; ni < 4; ni++)
                asm volatile(
                    "mma.sync.aligned.m16n8k8.row.col.f32.tf32.tf32.f32 "
                    "{%0,%1,%2,%3}, {%4,%5,%6,%7}, {%8,%9}, {%0,%1,%2,%3};"
                    : "+f"(c[mi][ni][0]), "+f"(c[mi][ni][1]),
                      "+f"(c[mi][ni][2]), "+f"(c[mi][ni][3])
                    : "r"(a[mi][0]), "r"(a[mi][1]), "r"(a[mi][2]), "r"(a[mi][3]),
                      "r"(b[ni][0]), "r"(b[ni][1]));
    }

#pragma unroll
    for (int mi = 0; mi < 2; mi++) {
#pragma unroll
        for (int half_m = 0; half_m < 2; half_m++) {
            const int row = wm + mi*16 + (lane>>2) + half_m*8;
            if (row < 126) {
                const int oyE = oy0 + row/42;
                const int oxE = row - (row/42)*42;
                float* op = out + (((size_t)n*42 + oyE)*42 + oxE)*64;
#pragma unroll
                for (int ni = 0; ni < 4; ni++) {
                    const int c0 = wn + ni*8 + 2*(lane&3);
                    float2 vv;
                    vv.x = fmaxf(c[mi][ni][half_m*2    ] + sbias[c0    ], 0.f);
                    vv.y = fmaxf(c[mi][ni][half_m*2 + 1] + sbias[c0 + 1], 0.f);
                    *(float2*)(op + c0) = vv;
                }
            }
        }
    }
}

// ---------------- generic bf16 mma implicit-GEMM conv, pipelined -----------
// NHWC f32 in -> NHWC f32 out. M = IMGS*MROWS*OW (pad 128), N = 64, K = 576.
// smem (uint32 words): sA[2] 128x36 (bf16x2, pitch 72 bf16), sB[2] 64x36, bias.
#define BF_SMEMW (2*4608 + 2*2304 + 64)
#define BF_SMEMB (BF_SMEMW*4)

template<int IH, int OH, int PADLOW, int MROWS, int IMGS, int NIMG>
__global__ void __launch_bounds__(256)
conv_mma_bf16(const float* __restrict__ in, const uint32_t* __restrict__ wb,
              const float* __restrict__ bias, float* __restrict__ out)
{
    extern __shared__ uint32_t smw[];
    uint32_t* sAb[2] = { smw, smw + 4608 };
    uint32_t* sBb[2] = { smw + 9216, smw + 11520 };
    float* sbias = (float*)(smw + 13824);

    constexpr int OW = OH;
    constexpr int MP = MROWS*OW;

    const int tid  = threadIdx.x;
    const int wid  = tid >> 5;
    const int lane = tid & 31;
    const int n0   = blockIdx.x * IMGS;
    const int oy0  = blockIdx.y * MROWS;

    if (tid < 64) sbias[tid] = bias[tid];

    const int wm = (wid & 3) * 32;
    const int wn = (wid >> 2) * 32;

    float c[2][4][4];
#pragma unroll
    for (int i = 0; i < 2; i++)
#pragma unroll
        for (int j = 0; j < 4; j++)
#pragma unroll
            for (int q = 0; q < 4; q++) c[i][j][q] = 0.f;

    // A staging mapping: 2 threads per position, 32 cins each
    const int p2   = tid >> 1;
    const int half = tid & 1;
    const int img  = p2 / MP;
    const int rem  = p2 - img*MP;
    const int oyl  = rem / OW;
    const int oxp  = rem - oyl*OW;
    const int oy   = oy0 + oyl;
    const int n    = n0 + img;
    const bool pv  = (img < IMGS) && (n < NIMG) && (oy < OH);
    const float* imgbase = in + (size_t)n*IH*IH*64;
    const uint4* bsrc = (const uint4*)wb;   // 512 uint4 per tap

    float4 pa[8];
    uint4  pb[2];

    // ---- prefetch + store for a tap ----
#define LOAD_TAP(tap_) do {                                                  \
        const int ky = (tap_) / 3, kx = (tap_) - 3*((tap_)/3);               \
        const int ry = 2*oy + ky - PADLOW;                                   \
        const int rx = 2*oxp + kx - PADLOW;                                  \
        const bool v = pv && ((unsigned)ry < (unsigned)IH)                   \
                          && ((unsigned)rx < (unsigned)IH);                  \
        const float* src = imgbase + ((size_t)ry*IH + rx)*64 + half*32;      \
        _Pragma("unroll")                                                    \
        for (int j = 0; j < 8; j++)                                          \
            pa[j] = v ? *(const float4*)(src + 4*j)                          \
                      : make_float4(0.f,0.f,0.f,0.f);                        \
        pb[0] = bsrc[(tap_)*512 + tid*2];                                    \
        pb[1] = bsrc[(tap_)*512 + tid*2 + 1];                                \
    } while (0)

#define STORE_TAP(buf_) do {                                                 \
        uint32_t* dA = sAb[buf_] + p2*36 + half*16;                          \
        _Pragma("unroll")                                                    \
        for (int i = 0; i < 4; i++) {                                        \
            uint4 u;                                                         \
            u.x = bf16x2(pa[2*i].x,   pa[2*i].y);                            \
            u.y = bf16x2(pa[2*i].z,   pa[2*i].w);                            \
            u.z = bf16x2(pa[2*i+1].x, pa[2*i+1].y);                          \
            u.w = bf16x2(pa[2*i+1].z, pa[2*i+1].w);                          \
            *(uint4*)(dA + i*4) = u;                                         \
        }                                                                    \
        uint32_t* dB = sBb[buf_] + (tid>>2)*36 + (tid&3)*8;                  \
        *(uint4*)dB       = pb[0];                                           \
        *(uint4*)(dB + 4) = pb[1];                                           \
    } while (0)

    LOAD_TAP(0);
    STORE_TAP(0);
    __syncthreads();

    int cur = 0;
    for (int tap = 0; tap < 9; tap++) {
        if (tap < 8) LOAD_TAP(tap + 1);

        const uint32_t* Ab = sAb[cur] + (wm + (lane>>2))*36 + (lane&3);
        const uint32_t* Bb = sBb[cur] + (wn + (lane>>2))*36 + (lane&3);
#pragma unroll
        for (int ks = 0; ks < 4; ks++) {
            uint32_t a[2][4];
#pragma unroll
            for (int mi = 0; mi < 2; mi++) {
                const uint32_t* ap = Ab + mi*16*36 + ks*8;
                a[mi][0] = ap[0];
                a[mi][1] = ap[8*36];
                a[mi][2] = ap[4];
                a[mi][3] = ap[8*36 + 4];
            }
            uint32_t b[4][2];
#pragma unroll
            for (int ni = 0; ni < 4; ni++) {
                const uint32_t* bp = Bb + ni*8*36 + ks*8;
                b[ni][0] = bp[0];
                b[ni][1] = bp[4];
            }
#pragma unroll
            for (int mi = 0; mi < 2; mi++)
#pragma unroll
                for (int ni = 0; ni < 4; ni++)
                    asm volatile(
                        "mma.sync.aligned.m16n8k16.row.col.f32.bf16.bf16.f32 "
                        "{%0,%1,%2,%3}, {%4,%5,%6,%7}, {%8,%9}, {%0,%1,%2,%3};"
                        : "+f"(c[mi][ni][0]), "+f"(c[mi][ni][1]),
                          "+f"(c[mi][ni][2]), "+f"(c[mi][ni][3])
                        : "r"(a[mi][0]), "r"(a[mi][1]), "r"(a[mi][2]), "r"(a[mi][3]),
                          "r"(b[ni][0]), "r"(b[ni][1]));
        }

        if (tap < 8) {
            STORE_TAP(cur ^ 1);
            __syncthreads();
            cur ^= 1;
        }
    }

    // epilogue: bias + relu, NHWC float2 stores
#pragma unroll
    for (int mi = 0; mi < 2; mi++) {
#pragma unroll
        for (int half_m = 0; half_m < 2; half_m++) {
            const int row = wm + mi*16 + (lane>>2) + half_m*8;
            const int imgE = row / MP;
            const int remE = row - imgE*MP;
            const int oyE  = oy0 + remE/OW;
            const int oxE  = remE - (remE/OW)*OW;
            const int nE   = n0 + imgE;
            if (imgE < IMGS && nE < NIMG && oyE < OH) {
                float* op = out + (((size_t)nE*OH + oyE)*OW + oxE)*64;
#pragma unroll
                for (int ni = 0; ni < 4; ni++) {
                    const int c0 = wn + ni*8 + 2*(lane&3);
                    float2 vv;
                    vv.x = fmaxf(c[mi][ni][half_m*2    ] + sbias[c0    ], 0.f);
                    vv.y = fmaxf(c[mi][ni][half_m*2 + 1] + sbias[c0 + 1], 0.f);
                    *(float2*)(op + c0) = vv;
                }
            }
        }
    }
#undef LOAD_TAP
#undef STORE_TAP
}

// ---------------- prototypes + inverse norms ----------------
__global__ void protos_kernel(const float* __restrict__ emb, const int* __restrict__ y,
                              float* __restrict__ protos, float* __restrict__ protoInv)
{
    const int b = blockIdx.x / 5, c = blockIdx.x % 5;
    const int tid = threadIdx.x;
    __shared__ int sels[25];
    if (tid < 25) sels[tid] = ((y[b*25 + tid] % 5) == c) ? 1 : 0;
    __syncthreads();

    float sq = 0.f;
    for (int d = tid; d < 2304; d += 256) {
        float v = 0.f;
#pragma unroll
        for (int s = 0; s < 25; s++)
            if (sels[s]) v += emb[(b*25 + s)*2304 + d];
        v = v / 5.0f;
        protos[(b*5 + c)*2304 + d] = v;
        sq += v*v;
    }
    __shared__ float red[256];
    red[tid] = sq; __syncthreads();
    for (int s = 128; s > 0; s >>= 1) {
        if (tid < s) red[tid] += red[tid + s];
        __syncthreads();
    }
    if (tid == 0) protoInv[b*5 + c] = 1.f / fmaxf(sqrtf(red[0]), 1e-8f);
}

// ---------------- cosine logits ----------------
__global__ void preds_kernel(const float* __restrict__ emb, const float* __restrict__ protos,
                             const float* __restrict__ protoInv, float* __restrict__ out)
{
    const int b = blockIdx.x / 75, t = blockIdx.x % 75;
    const int tid = threadIdx.x;
    float dot[5] = {0,0,0,0,0};
    float nsq = 0.f;
    const float* e = emb + (size_t)(200 + b*75 + t)*2304;
    for (int d = tid; d < 2304; d += 256) {
        float ev = e[d];
        nsq += ev*ev;
#pragma unroll
        for (int c = 0; c < 5; c++)
            dot[c] = fmaf(ev, protos[(b*5 + c)*2304 + d], dot[c]);
    }
    __shared__ float red[256];
    __shared__ float res[6];
    for (int q = 0; q < 6; q++) {
        red[tid] = (q == 0) ? nsq : dot[q-1];
        __syncthreads();
        for (int s = 128; s > 0; s >>= 1) {
            if (tid < s) red[tid] += red[tid + s];
            __syncthreads();
        }
        if (tid == 0) res[q] = red[0];
        __syncthreads();
    }
    if (tid < 5) {
        float inv_t = 1.f / fmaxf(sqrtf(res[0]), 1e-8f);
        out[(b*75 + t)*5 + tid] = res[1 + tid] * inv_t * protoInv[b*5 + tid];
    }
}

// ---------------- launch ----------------
extern "C" void kernel_launch(void* const* d_in, const int* in_sizes, int n_in,
                              void* d_out, int out_size)
{
    const float* xs = (const float*)d_in[0];
    const float* xt = (const float*)d_in[1];
    const int*   y  = (const int*)  d_in[2];
    const float* W1 = (const float*)d_in[3];
    const float* b1 = (const float*)d_in[4];
    const float* W2 = (const float*)d_in[5];
    const float* b2 = (const float*)d_in[6];
    const float* W3 = (const float*)d_in[7];
    const float* b3 = (const float*)d_in[8];
    const float* W4 = (const float*)d_in[9];
    const float* b4 = (const float*)d_in[10];
    float* out = (float*)d_out;

    float *bufA, *bufB, *bufC, *bufD, *pr, *pi, *w1t;
    uint32_t *w2b, *w3b, *w4b;
    cudaGetSymbolAddress((void**)&bufA, g_bufA);
    cudaGetSymbolAddress((void**)&bufB, g_bufB);
    cudaGetSymbolAddress((void**)&bufC, g_bufC);
    cudaGetSymbolAddress((void**)&bufD, g_bufD);
    cudaGetSymbolAddress((void**)&pr,   g_protos);
    cudaGetSymbolAddress((void**)&pi,   g_protoInv);
    cudaGetSymbolAddress((void**)&w1t,  g_w1t);
    cudaGetSymbolAddress((void**)&w2b,  g_w2b);
    cudaGetSymbolAddress((void**)&w3b,  g_w3b);
    cudaGetSymbolAddress((void**)&w4b,  g_w4b);

    static int smem_set = 0;
    if (!smem_set) {
        cudaFuncSetAttribute(conv_mma_bf16<42,21,0, 6,1,800>,
                             cudaFuncAttributeMaxDynamicSharedMemorySize, BF_SMEMB);
        cudaFuncSetAttribute(conv_mma_bf16<21,11,1, 11,1,800>,
                             cudaFuncAttributeMaxDynamicSharedMemorySize, BF_SMEMB);
        cudaFuncSetAttribute(conv_mma_bf16<11,6,1, 6,3,800>,
                             cudaFuncAttributeMaxDynamicSharedMemorySize, BF_SMEMB);
        smem_set = 1;
    }

    // prepack weights
    prepack_w1<<<(32*64 + 255)/256, 256>>>(W1, w1t);
    prepack_wb<<<(9*2048 + 255)/256, 256>>>(W2, w2b);
    prepack_wb<<<(9*2048 + 255)/256, 256>>>(W3, w3b);
    prepack_wb<<<(9*2048 + 255)/256, 256>>>(W4, w4b);

    // conv1: tf32 mma, NCHW in -> NHWC out
    conv1_mma<<<dim3(200,14), 256>>>(xs, w1t, b1, bufA);
    conv1_mma<<<dim3(600,14), 256>>>(xt, w1t, b1, bufA + (size_t)200*64*42*42);
    // conv2/3/4: bf16 mma, pipelined
    conv_mma_bf16<42,21,0, 6,1,800><<<dim3(800,4), 256, BF_SMEMB>>>(bufA, w2b, b2, bufB);
    conv_mma_bf16<21,11,1, 11,1,800><<<dim3(800,1), 256, BF_SMEMB>>>(bufB, w3b, b3, bufC);
    conv_mma_bf16<11,6,1, 6,3,800><<<dim3(267,1), 256, BF_SMEMB>>>(bufC, w4b, b4, bufD);
    // head
    protos_kernel<<<40, 256>>>(bufD, y, pr, pi);
    preds_kernel<<<600, 256>>>(bufD, pr, pi, out);
}

// round 15
// speedup vs baseline: 1.1434x; 1.1434x over previous
#include <cuda_runtime.h>
#include <math.h>
#include <stdint.h>

// ---------------- scratch ----------------
__device__ float g_bufA[800L*64*42*42];   // conv1 out (NHWC)
__device__ float g_bufB[800L*64*21*21];   // conv2 out (NHWC)
__device__ float g_bufC[800L*64*11*11];   // conv3 out (NHWC)
__device__ float g_bufD[800L*2304];       // conv4 out (embeddings, NHWC-flat)
__device__ float g_protos[8*5*2304];
__device__ float g_protoInv[8*5];
// prepacked tf32 weights
__device__ float g_w1t[32*64];            // conv1: [k(32)][cout]
__device__ float g_w2t[9*64*64];          // [tap][cin][cout] (rna tf32)
__device__ float g_w3t[9*64*64];
__device__ float g_w4t[9*64*64];

__device__ __forceinline__ float tf32_rna(float x) {
    uint32_t r; asm("cvt.rna.tf32.f32 %0, %1;" : "=r"(r) : "f"(x));
    return __uint_as_float(r);
}
__device__ __forceinline__ void cp_async16(uint32_t dst, const void* src, uint32_t src_bytes) {
    asm volatile("cp.async.ca.shared.global [%0], [%1], 16, %2;"
                 :: "r"(dst), "l"(src), "r"(src_bytes));
}
__device__ __forceinline__ void cp_commit() {
    asm volatile("cp.async.commit_group;" ::: "memory");
}
__device__ __forceinline__ void cp_wait0() {
    asm volatile("cp.async.wait_group 0;" ::: "memory");
}

// ---------------- weight prepacks ----------------
__global__ void prepack_w(const float* __restrict__ w, float* __restrict__ wt)
{
    int gid = blockIdx.x * 256 + threadIdx.x;          // 9*4096
    if (gid >= 9*4096) return;
    int tap  = gid >> 12;
    int r    = gid & 4095;
    int cin  = r >> 6;
    int cout = r & 63;
    wt[gid] = tf32_rna(w[(cout*64 + cin)*9 + tap]);
}

__global__ void prepack_w1(const float* __restrict__ w, float* __restrict__ wt)
{
    int gid = blockIdx.x * 256 + threadIdx.x;          // 32*64
    if (gid >= 32*64) return;
    int k    = gid >> 6;
    int cout = gid & 63;
    float v = 0.f;
    if (k < 27) {
        int c = k / 9, tap = k - 9*c;
        v = tf32_rna(w[(cout*3 + c)*9 + tap]);
    }
    wt[gid] = v;
}

// ---------------- conv1: mma.sync tf32, NCHW in -> NHWC out ----------------
#define A1P 36
#define B1P 72

__global__ void __launch_bounds__(256)
conv1_mma(const float* __restrict__ in, const float* __restrict__ wt,
          const float* __restrict__ bias, float* __restrict__ out)
{
    __shared__ float sA[128*A1P];
    __shared__ float sB[32*B1P];
    __shared__ float sbias[64];

    const int tid  = threadIdx.x;
    const int wid  = tid >> 5;
    const int lane = tid & 31;
    const int n    = blockIdx.x;
    const int oy0  = blockIdx.y * 3;

    if (tid < 64) sbias[tid] = bias[tid];

    // ---- stage A: 2 threads per position, 14 taps each ----
    {
        const int p   = tid >> 1;
        const int h   = tid & 1;
        const int oyl = p / 42;
        const int oxp = p - oyl*42;
        const int oy  = oy0 + oyl;
        const bool pv = p < 126;
        const float* ib = in + (size_t)n*3*84*84;
        float* dst = sA + p*A1P;
        for (int k = h*14; k < h*14 + 14; k++) {
            if (k < 27) {
                int c = k / 9, rem = k - 9*c;
                int ky = rem / 3, kx = rem - 3*(rem/3);
                int ry = 2*oy + ky, rx = 2*oxp + kx;
                float v = 0.f;
                if (pv && ry < 84 && rx < 84)
                    v = ib[(c*84 + ry)*84 + rx];
                dst[k] = tf32_rna(v);
            }
        }
        if (h) { dst[27]=0.f; dst[28]=0.f; dst[29]=0.f; dst[30]=0.f; dst[31]=0.f; }
    }
    if (tid < 128) {
        const float4* bsrc = (const float4*)wt;
#pragma unroll
        for (int i = 0; i < 4; i++) {
            int idx = tid + i*128;
            int row = idx >> 4, col4 = idx & 15;
            *(float4*)(sB + row*B1P + col4*4) = bsrc[idx];
        }
    }
    __syncthreads();

    const int wm = (wid & 3) * 32;
    const int wn = (wid >> 2) * 32;

    float c[2][4][4];
#pragma unroll
    for (int i = 0; i < 2; i++)
#pragma unroll
        for (int j = 0; j < 4; j++)
#pragma unroll
            for (int q = 0; q < 4; q++) c[i][j][q] = 0.f;

#pragma unroll
    for (int ks = 0; ks < 4; ks++) {
        const int k0 = ks*8;
        uint32_t a[2][4];
#pragma unroll
        for (int mi = 0; mi < 2; mi++) {
            const float* ap = sA + (wm + mi*16 + (lane>>2))*A1P + k0 + (lane&3);
            a[mi][0] = __float_as_uint(ap[0]);
            a[mi][1] = __float_as_uint(ap[8*A1P]);
            a[mi][2] = __float_as_uint(ap[4]);
            a[mi][3] = __float_as_uint(ap[8*A1P + 4]);
        }
        uint32_t b[4][2];
#pragma unroll
        for (int ni = 0; ni < 4; ni++) {
            const float* bp = sB + (k0 + (lane&3))*B1P + wn + ni*8 + (lane>>2);
            b[ni][0] = __float_as_uint(bp[0]);
            b[ni][1] = __float_as_uint(bp[4*B1P]);
        }
#pragma unroll
        for (int mi = 0; mi < 2; mi++)
#pragma unroll
            for (int ni = 0; ni < 4; ni++)
                asm volatile(
                    "mma.sync.aligned.m16n8k8.row.col.f32.tf32.tf32.f32 "
                    "{%0,%1,%2,%3}, {%4,%5,%6,%7}, {%8,%9}, {%0,%1,%2,%3};"
                    : "+f"(c[mi][ni][0]), "+f"(c[mi][ni][1]),
                      "+f"(c[mi][ni][2]), "+f"(c[mi][ni][3])
                    : "r"(a[mi][0]), "r"(a[mi][1]), "r"(a[mi][2]), "r"(a[mi][3]),
                      "r"(b[ni][0]), "r"(b[ni][1]));
    }

#pragma unroll
    for (int mi = 0; mi < 2; mi++) {
#pragma unroll
        for (int half_m = 0; half_m < 2; half_m++) {
            const int row = wm + mi*16 + (lane>>2) + half_m*8;
            if (row < 126) {
                const int oyE = oy0 + row/42;
                const int oxE = row - (row/42)*42;
                float* op = out + (((size_t)n*42 + oyE)*42 + oxE)*64;
#pragma unroll
                for (int ni = 0; ni < 4; ni++) {
                    const int c0 = wn + ni*8 + 2*(lane&3);
                    float2 vv;
                    vv.x = fmaxf(c[mi][ni][half_m*2    ] + sbias[c0    ], 0.f);
                    vv.y = fmaxf(c[mi][ni][half_m*2 + 1] + sbias[c0 + 1], 0.f);
                    *(float2*)(op + c0) = vv;
                }
            }
        }
    }
}

// ---------------- generic tf32 mma implicit-GEMM conv, cp.async pipelined --
// NHWC in -> NHWC out. M = IMGS*MROWS*OW (pad 128), N=64, K=576.
// Double-buffered smem staged via cp.async (no register round-trip).
// A operands are raw f32 (tf32 HW truncation); B prepacked rna-tf32.
#define AP 68
#define BP 72
#define MMA_SMEMB ((2*128*AP + 2*64*BP + 64)*4)

template<int IH, int OH, int PADLOW, int MROWS, int IMGS, int NIMG>
__global__ void __launch_bounds__(256)
conv_mma(const float* __restrict__ in, const float* __restrict__ wt,
         const float* __restrict__ bias, float* __restrict__ out)
{
    extern __shared__ float smf[];
    float* sAf[2] = { smf, smf + 128*AP };
    float* sBf[2] = { smf + 2*128*AP, smf + 2*128*AP + 64*BP };
    float* sbias  = smf + 2*128*AP + 2*64*BP;

    constexpr int OW = OH;
    constexpr int MP = MROWS*OW;

    const int tid  = threadIdx.x;
    const int wid  = tid >> 5;
    const int lane = tid & 31;
    const int n0   = blockIdx.x * IMGS;
    const int oy0  = blockIdx.y * MROWS;

    if (tid < 64) sbias[tid] = bias[tid];

    const int wm = (wid & 3) * 32;
    const int wn = (wid >> 2) * 32;

    float c[2][4][4];
#pragma unroll
    for (int i = 0; i < 2; i++)
#pragma unroll
        for (int j = 0; j < 4; j++)
#pragma unroll
            for (int q = 0; q < 4; q++) c[i][j][q] = 0.f;

    // staging mapping: 2 threads per position, 32 cins (8x16B) each
    const int p2   = tid >> 1;
    const int half = tid & 1;
    const int img  = p2 / MP;
    const int rem  = p2 - img*MP;
    const int oyl  = rem / OW;
    const int oxp  = rem - oyl*OW;
    const int oy   = oy0 + oyl;
    const int n    = n0 + img;
    const bool pv  = (img < IMGS) && (n < NIMG) && (oy < OH);
    const float* imgbase = in + (size_t)n*IH*IH*64;

    const uint32_t dA_base[2] = {
        (uint32_t)__cvta_generic_to_shared(sAf[0] + p2*AP + half*32),
        (uint32_t)__cvta_generic_to_shared(sAf[1] + p2*AP + half*32) };
    // B: 4x16B per thread; idx = tid + i*256
    uint32_t dB_base[2];
    {
        int idx0 = tid;
        int row = idx0 >> 4, col4 = idx0 & 15;
        dB_base[0] = (uint32_t)__cvta_generic_to_shared(sBf[0] + row*BP + col4*4);
        dB_base[1] = (uint32_t)__cvta_generic_to_shared(sBf[1] + row*BP + col4*4);
    }

#define ISSUE_TAP(tap_, buf_) do {                                           \
        const int ky = (tap_) / 3, kx = (tap_) - 3*((tap_)/3);               \
        const int ry = 2*oy + ky - PADLOW;                                   \
        const int rx = 2*oxp + kx - PADLOW;                                  \
        const bool v = pv && ((unsigned)ry < (unsigned)IH)                   \
                          && ((unsigned)rx < (unsigned)IH);                  \
        const float* src = v ? imgbase + ((size_t)ry*IH + rx)*64 + half*32   \
                             : imgbase;                                      \
        const uint32_t szr = v ? 16u : 0u;                                   \
        _Pragma("unroll")                                                    \
        for (int j = 0; j < 8; j++)                                          \
            cp_async16(dA_base[buf_] + j*16, src + 4*j, szr);                \
        _Pragma("unroll")                                                    \
        for (int i = 0; i < 4; i++) {                                        \
            int idx = tid + i*256;                                           \
            int brow = idx >> 4, bcol4 = idx & 15;                           \
            cp_async16(dB_base[buf_] + ((brow*BP + bcol4*4) -                \
                       ((tid>>4)*BP + (tid&15)*4))*4,                        \
                       wt + (tap_)*4096 + idx*4, 16u);                       \
        }                                                                    \
        cp_commit();                                                         \
    } while (0)

    ISSUE_TAP(0, 0);
    cp_wait0();
    __syncthreads();

    int cur = 0;
    for (int tap = 0; tap < 9; tap++) {
        if (tap < 8) ISSUE_TAP(tap + 1, cur ^ 1);

        const float* Af = sAf[cur];
        const float* Bf = sBf[cur];
#pragma unroll
        for (int ks = 0; ks < 8; ks++) {
            const int k0 = ks*8;
            uint32_t a[2][4];
#pragma unroll
            for (int mi = 0; mi < 2; mi++) {
                const float* ap = Af + (wm + mi*16 + (lane>>2))*AP + k0 + (lane&3);
                a[mi][0] = __float_as_uint(ap[0]);
                a[mi][1] = __float_as_uint(ap[8*AP]);
                a[mi][2] = __float_as_uint(ap[4]);
                a[mi][3] = __float_as_uint(ap[8*AP + 4]);
            }
            uint32_t b[4][2];
#pragma unroll
            for (int ni = 0; ni < 4; ni++) {
                const float* bp = Bf + (k0 + (lane&3))*BP + wn + ni*8 + (lane>>2);
                b[ni][0] = __float_as_uint(bp[0]);
                b[ni][1] = __float_as_uint(bp[4*BP]);
            }
#pragma unroll
            for (int mi = 0; mi < 2; mi++)
#pragma unroll
                for (int ni = 0; ni < 4; ni++)
                    asm volatile(
                        "mma.sync.aligned.m16n8k8.row.col.f32.tf32.tf32.f32 "
                        "{%0,%1,%2,%3}, {%4,%5,%6,%7}, {%8,%9}, {%0,%1,%2,%3};"
                        : "+f"(c[mi][ni][0]), "+f"(c[mi][ni][1]),
                          "+f"(c[mi][ni][2]), "+f"(c[mi][ni][3])
                        : "r"(a[mi][0]), "r"(a[mi][1]), "r"(a[mi][2]), "r"(a[mi][3]),
                          "r"(b[ni][0]), "r"(b[ni][1]));
        }

        if (tap < 8) {
            cp_wait0();
            __syncthreads();
            cur ^= 1;
        }
    }

    // epilogue
#pragma unroll
    for (int mi = 0; mi < 2; mi++) {
#pragma unroll
        for (int half_m = 0; half_m < 2; half_m++) {
            const int row = wm + mi*16 + (lane>>2) + half_m*8;
            const int imgE = row / MP;
            const int remE = row - imgE*MP;
            const int oyE  = oy0 + remE/OW;
            const int oxE  = remE - (remE/OW)*OW;
            const int nE   = n0 + imgE;
            if (imgE < IMGS && nE < NIMG && oyE < OH) {
                float* op = out + (((size_t)nE*OH + oyE)*OW + oxE)*64;
#pragma unroll
                for (int ni = 0; ni < 4; ni++) {
                    const int c0 = wn + ni*8 + 2*(lane&3);
                    float2 vv;
                    vv.x = fmaxf(c[mi][ni][half_m*2    ] + sbias[c0    ], 0.f);
                    vv.y = fmaxf(c[mi][ni][half_m*2 + 1] + sbias[c0 + 1], 0.f);
                    *(float2*)(op + c0) = vv;
                }
            }
        }
    }
#undef ISSUE_TAP
}

// ---------------- prototypes + inverse norms ----------------
__global__ void protos_kernel(const float* __restrict__ emb, const int* __restrict__ y,
                              float* __restrict__ protos, float* __restrict__ protoInv)
{
    const int b = blockIdx.x / 5, c = blockIdx.x % 5;
    const int tid = threadIdx.x;
    __shared__ int sels[25];
    if (tid < 25) sels[tid] = ((y[b*25 + tid] % 5) == c) ? 1 : 0;
    __syncthreads();

    float sq = 0.f;
    for (int d = tid; d < 2304; d += 256) {
        float v = 0.f;
#pragma unroll
        for (int s = 0; s < 25; s++)
            if (sels[s]) v += emb[(b*25 + s)*2304 + d];
        v = v / 5.0f;
        protos[(b*5 + c)*2304 + d] = v;
        sq += v*v;
    }
    __shared__ float red[256];
    red[tid] = sq; __syncthreads();
    for (int s = 128; s > 0; s >>= 1) {
        if (tid < s) red[tid] += red[tid + s];
        __syncthreads();
    }
    if (tid == 0) protoInv[b*5 + c] = 1.f / fmaxf(sqrtf(red[0]), 1e-8f);
}

// ---------------- cosine logits ----------------
__global__ void preds_kernel(const float* __restrict__ emb, const float* __restrict__ protos,
                             const float* __restrict__ protoInv, float* __restrict__ out)
{
    const int b = blockIdx.x / 75, t = blockIdx.x % 75;
    const int tid = threadIdx.x;
    float dot[5] = {0,0,0,0,0};
    float nsq = 0.f;
    const float* e = emb + (size_t)(200 + b*75 + t)*2304;
    for (int d = tid; d < 2304; d += 256) {
        float ev = e[d];
        nsq += ev*ev;
#pragma unroll
        for (int c = 0; c < 5; c++)
            dot[c] = fmaf(ev, protos[(b*5 + c)*2304 + d], dot[c]);
    }
    __shared__ float red[256];
    __shared__ float res[6];
    for (int q = 0; q < 6; q++) {
        red[tid] = (q == 0) ? nsq : dot[q-1];
        __syncthreads();
        for (int s = 128; s > 0; s >>= 1) {
            if (tid < s) red[tid] += red[tid + s];
            __syncthreads();
        }
        if (tid == 0) res[q] = red[0];
        __syncthreads();
    }
    if (tid < 5) {
        float inv_t = 1.f / fmaxf(sqrtf(res[0]), 1e-8f);
        out[(b*75 + t)*5 + tid] = res[1 + tid] * inv_t * protoInv[b*5 + tid];
    }
}

// ---------------- launch ----------------
extern "C" void kernel_launch(void* const* d_in, const int* in_sizes, int n_in,
                              void* d_out, int out_size)
{
    const float* xs = (const float*)d_in[0];
    const float* xt = (const float*)d_in[1];
    const int*   y  = (const int*)  d_in[2];
    const float* W1 = (const float*)d_in[3];
    const float* b1 = (const float*)d_in[4];
    const float* W2 = (const float*)d_in[5];
    const float* b2 = (const float*)d_in[6];
    const float* W3 = (const float*)d_in[7];
    const float* b3 = (const float*)d_in[8];
    const float* W4 = (const float*)d_in[9];
    const float* b4 = (const float*)d_in[10];
    float* out = (float*)d_out;

    float *bufA, *bufB, *bufC, *bufD, *pr, *pi, *w1t, *w2t, *w3t, *w4t;
    cudaGetSymbolAddress((void**)&bufA, g_bufA);
    cudaGetSymbolAddress((void**)&bufB, g_bufB);
    cudaGetSymbolAddress((void**)&bufC, g_bufC);
    cudaGetSymbolAddress((void**)&bufD, g_bufD);
    cudaGetSymbolAddress((void**)&pr,   g_protos);
    cudaGetSymbolAddress((void**)&pi,   g_protoInv);
    cudaGetSymbolAddress((void**)&w1t,  g_w1t);
    cudaGetSymbolAddress((void**)&w2t,  g_w2t);
    cudaGetSymbolAddress((void**)&w3t,  g_w3t);
    cudaGetSymbolAddress((void**)&w4t,  g_w4t);

    static int smem_set = 0;
    if (!smem_set) {
        cudaFuncSetAttribute(conv_mma<42,21,0, 6,1,800>,
                             cudaFuncAttributeMaxDynamicSharedMemorySize, MMA_SMEMB);
        cudaFuncSetAttribute(conv_mma<21,11,1, 11,1,800>,
                             cudaFuncAttributeMaxDynamicSharedMemorySize, MMA_SMEMB);
        cudaFuncSetAttribute(conv_mma<11,6,1, 6,3,800>,
                             cudaFuncAttributeMaxDynamicSharedMemorySize, MMA_SMEMB);
        smem_set = 1;
    }

    // prepack tf32 weights
    prepack_w1<<<(32*64 + 255)/256, 256>>>(W1, w1t);
    prepack_w<<<(9*4096 + 255)/256, 256>>>(W2, w2t);
    prepack_w<<<(9*4096 + 255)/256, 256>>>(W3, w3t);
    prepack_w<<<(9*4096 + 255)/256, 256>>>(W4, w4t);

    // conv1: tf32 mma, NCHW in -> NHWC out
    conv1_mma<<<dim3(200,14), 256>>>(xs, w1t, b1, bufA);
    conv1_mma<<<dim3(600,14), 256>>>(xt, w1t, b1, bufA + (size_t)200*64*42*42);
    // conv2/3/4: tf32 mma, cp.async pipelined
    conv_mma<42,21,0, 6,1,800><<<dim3(800,4), 256, MMA_SMEMB>>>(bufA, w2t, b2, bufB);
    conv_mma<21,11,1, 11,1,800><<<dim3(800,1), 256, MMA_SMEMB>>>(bufB, w3t, b3, bufC);
    conv_mma<11,6,1, 6,3,800><<<dim3(267,1), 256, MMA_SMEMB>>>(bufC, w4t, b4, bufD);
    // head
    protos_kernel<<<40, 256>>>(bufD, y, pr, pi);
    preds_kernel<<<600, 256>>>(bufD, pr, pi, out);
}